// round 11
// baseline (speedup 1.0000x reference)
#include <cuda_runtime.h>
#include <math.h>
#include <stdint.h>
#include <stddef.h>

#define NRAYS 2048
#define NSAMP 128
#define NS (NRAYS * NSAMP)   // 262144 samples per pass

// ---------------- static scratch (no allocations allowed) ----------------
__device__ float g_enc[NRAYS * 96 * 128];   // block-transposed IPE: [ray][k][m]
__device__ float g_rf[NS * 6];              // raw heads per sample
__device__ float g_direnc[NRAYS * 27];
__device__ float g_raynorm[NRAYS];
__device__ float g_raybias[NRAYS * 128];
__device__ float g_weights[NS];
__device__ float g_mus[NS];
__device__ float g_smsig[NS];
__device__ float g_lt[NS];
__device__ float g_pib[NS];
__device__ float g_tfine[NRAYS * 129];
__device__ float g_cdf[NRAYS * 129];
__device__ float g_pdfn[NS];

// fused-kernel smem layout (M=64 samples per block):
//   act  : 256 x 68 fp32                     ( 69632 B)
//   BpkH : 2 buf x 8 k2 x 264 u32 (bf16x2)   ( 16896 B)
//   BpkL : same                              ( 16896 B)
#define ACT_STRIDE 68
#define ACT_WORDS (256 * ACT_STRIDE)
#define BPK_WORDS (2 * 8 * 264)
#define FUSED_SMEM ((ACT_WORDS + 2 * BPK_WORDS) * 4)   // 103424 B -> 2 blocks/SM

// ---------------- helpers ----------------
__device__ __forceinline__ float fast_sigmoid(float x) {
    return 1.0f / (1.0f + __expf(-x));
}
__device__ __forceinline__ float acdf_(float x) {
    float x3 = x * x * x;
    float z = 0.7978845608028654f * (x + 0.044715f * x3);
    return 1.0f / (1.0f + __expf(-2.0f * z));
}
// pack {lower = bf16(x0) [k even], upper = bf16(x1) [k odd]}
__device__ __forceinline__ uint32_t pack_bf16x2(float x0, float x1) {
    uint32_t d;
    asm("cvt.rn.bf16x2.f32 %0, %1, %2;" : "=r"(d) : "f"(x1), "f"(x0));
    return d;
}
// split pair (x0, x1) into bf16 hi-pack + bf16 lo-pack (residuals)
__device__ __forceinline__ void split_pair(float x0, float x1, uint32_t& hpk, uint32_t& lpk) {
    hpk = pack_bf16x2(x0, x1);
    float h0 = __uint_as_float(hpk << 16);
    float h1 = __uint_as_float(hpk & 0xffff0000u);
    lpk = pack_bf16x2(x0 - h0, x1 - h1);
}
__device__ __forceinline__ void cp16(void* s, const void* g) {
    uint32_t sa = (uint32_t)__cvta_generic_to_shared(s);
    asm volatile("cp.async.ca.shared.global [%0], [%1], 16;" :: "r"(sa), "l"(g));
}
__device__ __forceinline__ void cp_commit() {
    asm volatile("cp.async.commit_group;" ::: "memory");
}
__device__ __forceinline__ void cp_wait0() {
    asm volatile("cp.async.wait_group 0;" ::: "memory");
}

#define MMA_BF16(d, a0, a1, a2, a3, b0, b1)                                  \
    asm volatile(                                                            \
        "mma.sync.aligned.m16n8k16.row.col.f32.bf16.bf16.f32 "               \
        "{%0,%1,%2,%3}, {%4,%5,%6,%7}, {%8,%9}, {%0,%1,%2,%3};"              \
        : "+f"(d[0]), "+f"(d[1]), "+f"(d[2]), "+f"(d[3])                     \
        : "r"(a0), "r"(a1), "r"(a2), "r"(a3), "r"(b0), "r"(b1))

// ---------------- ray setup ----------------
__global__ void ray_setup_kernel(const float* __restrict__ rd) {
    int r = blockIdx.x * blockDim.x + threadIdx.x;
    if (r >= NRAYS) return;
    float x = rd[r * 3 + 0], y = rd[r * 3 + 1], z = rd[r * 3 + 2];
    float n = sqrtf(x * x + y * y + z * z);
    g_raynorm[r] = n;
    float inv = 1.0f / n;
    float v[3] = {x * inv, y * inv, z * inv};
    float* de = g_direnc + r * 27;
    de[0] = v[0]; de[1] = v[1]; de[2] = v[2];
#pragma unroll
    for (int f = 0; f < 4; f++) {
        float fr = (float)(1 << f);
#pragma unroll
        for (int k = 0; k < 3; k++) {
            float xx = v[k] * fr;
            de[3 + f * 3 + k]  = sinf(xx);
            de[15 + f * 3 + k] = cosf(xx);
        }
    }
}

// per-ray bias for Wd layer: bd[o] + sum_j direnc[j] * Wd[256+j][o]
__global__ void ray_bias_kernel(const float* __restrict__ Wd, const float* __restrict__ bd) {
    int r = blockIdx.x;
    int o = threadIdx.x;
    __shared__ float de[27];
    if (o < 27) de[o] = g_direnc[r * 27 + o];
    __syncthreads();
    float a = bd[o];
#pragma unroll
    for (int j = 0; j < 27; j++) a += de[j] * Wd[(256 + j) * 128 + o];
    g_raybias[r * 128 + o] = a;
}

// ---------------- IPE, block-transposed output [ray][k][m] ----------------
__global__ void ipe_kernel(const float* __restrict__ ro, const float* __restrict__ rd,
                           const float* __restrict__ rr, const float* __restrict__ tsrc) {
    int s = blockIdx.x * blockDim.x + threadIdx.x;
    if (s >= NS) return;
    int ray = s >> 7, i = s & 127;
    float t0, t1;
    if (tsrc) {
        t0 = tsrc[ray * 129 + i];
        t1 = tsrc[ray * 129 + i + 1];
    } else {
        t0 = 2.0f + 4.0f * ((float)i / 128.0f);
        t1 = 2.0f + 4.0f * ((float)(i + 1) / 128.0f);
    }
    float c  = 0.5f * (t0 + t1);
    float dd = 0.5f * (t1 - t0);
    float d2s = dd * dd;
    float d4  = d2s * d2s;
    float c2  = c * c;
    float denom = 3.0f * c2 + d2s;
    float t_mean = c + 2.0f * c * d2s / denom;
    float t_var  = d2s * (1.0f / 3.0f) - (4.0f / 15.0f) * (d4 * (12.0f * c2 - d2s)) / (denom * denom);
    float rrv = rr[ray];
    float r_var = rrv * rrv * (c2 * 0.25f + (5.0f / 12.0f) * d2s - (4.0f / 15.0f) * d4 / denom);

    float rdv[3] = {rd[ray * 3 + 0], rd[ray * 3 + 1], rd[ray * 3 + 2]};
    float rov[3] = {ro[ray * 3 + 0], ro[ray * 3 + 1], ro[ray * 3 + 2]};
    float dn2 = rdv[0] * rdv[0] + rdv[1] * rdv[1] + rdv[2] * rdv[2];
    float invd2 = 1.0f / fmaxf(dn2, 1e-10f);
    float mean[3], cov[3];
#pragma unroll
    for (int k = 0; k < 3; k++) {
        mean[k] = rov[k] + rdv[k] * t_mean;
        float dok = rdv[k] * rdv[k];
        cov[k] = t_var * dok + r_var * (1.0f - dok * invd2);
    }

    float* e = g_enc + (size_t)ray * 96 * 128;
    int m = i;
    float scale = 1.0f;
#pragma unroll 4
    for (int deg = 0; deg < 16; deg++) {
        float sc2 = scale * scale;
#pragma unroll
        for (int k = 0; k < 3; k++) {
            int idx = deg * 3 + k;
            float sv, cv;
            float yv = cov[k] * sc2;
            if (yv > 60.0f) {
                sv = 0.0f; cv = 0.0f;
            } else {
                float att = __expf(-0.5f * yv);
                float y = mean[k] * scale;
                double kd = rint((double)y * 0.15915494309189535);
                float rp = (float)((double)y - kd * 6.283185307179586);
                sv = __sinf(rp) * att;
                cv = __cosf(rp) * att;
            }
            e[(size_t)idx * 128 + m]        = sv;
            e[(size_t)(48 + idx) * 128 + m] = cv;
        }
        scale *= 2.0f;
    }
}

// ---------------- fused-MLP layer, bf16x3 m16n8k16, M=64 ----------------
// 256 threads, 8 warps as 4(m) x 2(n); warp tile m16 x (NT*8). N total = NT*16.
// act[k][m] raw fp32, stride 68; W streamed, split hi/lo bf16x2 k-pairs at stash.
template<int NT, bool RELU>
__device__ __forceinline__ void run_layer(
    float* __restrict__ act, uint32_t* __restrict__ BbH, uint32_t* __restrict__ BbL,
    const float* __restrict__ Wl, const float* __restrict__ bias,
    int K, int tid, int wid, int lane)
{
    constexpr int NCOLS = NT * 16;
    constexpr int PER = NCOLS / 32;          // packed words per thread per stage (8 or 4)
    const int wm = (wid & 3) * 16;
    const int wn = (wid >> 2) * (NT * 8);
    const int g  = lane >> 2;
    const int t4 = lane & 3;

    const int idx0 = tid * PER;
    const int k2   = idx0 / NCOLS;           // 0..7
    const int nn   = idx0 % NCOLS;
    const float* Wr0 = Wl + (size_t)(2 * k2) * NCOLS + nn;
    const float* Wr1 = Wr0 + NCOLS;
    uint32_t* stH = BbH + k2 * 264 + nn;
    uint32_t* stL = BbL + k2 * 264 + nn;

    float d[NT][4];
#pragma unroll
    for (int nt = 0; nt < NT; nt++)
#pragma unroll
        for (int q = 0; q < 4; q++) d[nt][q] = 0.0f;

    const int nStage = K >> 4;

    float p0[PER], p1[PER];

    auto loadW = [&](int s) {
        const float* a0 = Wr0 + (size_t)s * 16 * NCOLS;
        const float* a1 = Wr1 + (size_t)s * 16 * NCOLS;
        if constexpr (PER == 8) {
            float4 u0 = *(const float4*)a0;
            float4 u1 = *(const float4*)(a0 + 4);
            float4 v0 = *(const float4*)a1;
            float4 v1 = *(const float4*)(a1 + 4);
            p0[0]=u0.x; p0[1]=u0.y; p0[2]=u0.z; p0[3]=u0.w;
            p0[4]=u1.x; p0[5]=u1.y; p0[6]=u1.z; p0[7]=u1.w;
            p1[0]=v0.x; p1[1]=v0.y; p1[2]=v0.z; p1[3]=v0.w;
            p1[4]=v1.x; p1[5]=v1.y; p1[6]=v1.z; p1[7]=v1.w;
        } else {
            float4 u = *(const float4*)a0; p0[0]=u.x; p0[1]=u.y; p0[2]=u.z; p0[3]=u.w;
            float4 v = *(const float4*)a1; p1[0]=v.x; p1[1]=v.y; p1[2]=v.z; p1[3]=v.w;
        }
    };
    auto stash = [&](int b) {
        uint32_t h[PER], l[PER];
#pragma unroll
        for (int j = 0; j < PER; j++) split_pair(p0[j], p1[j], h[j], l[j]);
        if constexpr (PER == 8) {
            *(uint4*)(stH + b * 2112)     = make_uint4(h[0], h[1], h[2], h[3]);
            *(uint4*)(stH + b * 2112 + 4) = make_uint4(h[4], h[5], h[6], h[7]);
            *(uint4*)(stL + b * 2112)     = make_uint4(l[0], l[1], l[2], l[3]);
            *(uint4*)(stL + b * 2112 + 4) = make_uint4(l[4], l[5], l[6], l[7]);
        } else {
            *(uint4*)(stH + b * 2112) = make_uint4(h[0], h[1], h[2], h[3]);
            *(uint4*)(stL + b * 2112) = make_uint4(l[0], l[1], l[2], l[3]);
        }
    };

    loadW(0);
    stash(0);
    __syncthreads();

    for (int s = 0; s < nStage; ++s) {
        const int buf = s & 1;
        if (s + 1 < nStage) loadW(s + 1);

        // A fragments: k-pairs split to bf16 hi/lo at load
        uint32_t aH[4], aL[4];
        {
            const float* A0 = act + (size_t)(s * 16 + 2 * t4) * ACT_STRIDE;
            const float* A8 = A0 + 8 * ACT_STRIDE;
            const int ma = wm + g, mb = ma + 8;
            split_pair(A0[ma], A0[ACT_STRIDE + ma], aH[0], aL[0]);
            split_pair(A0[mb], A0[ACT_STRIDE + mb], aH[1], aL[1]);
            split_pair(A8[ma], A8[ACT_STRIDE + ma], aH[2], aL[2]);
            split_pair(A8[mb], A8[ACT_STRIDE + mb], aH[3], aL[3]);
        }

        const uint32_t* bh = BbH + buf * 2112 + t4 * 264;
        const uint32_t* bl = BbL + buf * 2112 + t4 * 264;
#pragma unroll
        for (int nt = 0; nt < NT; nt++) {
            const int n0 = wn + nt * 8 + g;
            uint32_t bH0 = bh[n0];
            uint32_t bH1 = bh[4 * 264 + n0];
            uint32_t bL0 = bl[n0];
            uint32_t bL1 = bl[4 * 264 + n0];
            MMA_BF16(d[nt], aH[0], aH[1], aH[2], aH[3], bH0, bH1);
            MMA_BF16(d[nt], aL[0], aL[1], aL[2], aL[3], bH0, bH1);
            MMA_BF16(d[nt], aH[0], aH[1], aH[2], aH[3], bL0, bL1);
        }

        if (s + 1 < nStage) {
            stash(buf ^ 1);
            __syncthreads();
        }
    }

    __syncthreads();   // all act reads complete before overwrite

    // transposed epilogue: act[col][row] = activation(value + bias)
#pragma unroll
    for (int nt = 0; nt < NT; nt++) {
        const int c0 = wn + nt * 8 + 2 * t4;
        const int r0 = wm + g;
        float b0v = bias[c0], b1v = bias[c0 + 1];
        float v0 = d[nt][0] + b0v;
        float v1 = d[nt][1] + b1v;
        float v2 = d[nt][2] + b0v;
        float v3 = d[nt][3] + b1v;
        if (RELU) {
            v0 = fmaxf(v0, 0.0f); v1 = fmaxf(v1, 0.0f);
            v2 = fmaxf(v2, 0.0f); v3 = fmaxf(v3, 0.0f);
        }
        act[(size_t)c0 * ACT_STRIDE + r0]           = v0;
        act[(size_t)(c0 + 1) * ACT_STRIDE + r0]     = v1;
        act[(size_t)c0 * ACT_STRIDE + r0 + 8]       = v2;
        act[(size_t)(c0 + 1) * ACT_STRIDE + r0 + 8] = v3;
    }
    __syncthreads();
}

// ---------------- fused MLP: one block = 64 samples (half ray) ----------------
template<bool COARSE>
__global__ void __launch_bounds__(256, 2) fused_mlp(
    const float* __restrict__ enc_t,
    const float* __restrict__ W0, const float* __restrict__ b0,
    const float* __restrict__ Wh, const float* __restrict__ bh,
    const float* __restrict__ Ws, const float* __restrict__ bs,
    const float* __restrict__ Wm, const float* __restrict__ bm,
    const float* __restrict__ Wb, const float* __restrict__ bb,
    const float* __restrict__ Wd, const float* __restrict__ rbias_all,
    const float* __restrict__ Wr, const float* __restrict__ br,
    float* __restrict__ RF)
{
    extern __shared__ float smem[];
    float* act = smem;
    uint32_t* BbH = (uint32_t*)(smem + ACT_WORDS);
    uint32_t* BbL = BbH + BPK_WORDS;

    const int tid  = threadIdx.x;
    const int wid  = tid >> 5;
    const int lane = tid & 31;
    const int blk  = blockIdx.x;
    const int ray  = blk >> 1;
    const int mbase = (blk & 1) * 64;

    // load enc half-tile [96][64] into act
    {
        const float* ebase = enc_t + (size_t)ray * 96 * 128 + mbase;
        for (int i = tid; i < 96 * 16; i += 256) {
            int k = i >> 4, m4 = (i & 15) * 4;
            cp16(act + (size_t)k * ACT_STRIDE + m4, ebase + k * 128 + m4);
        }
        cp_commit(); cp_wait0();
    }
    __syncthreads();

    run_layer<16, true>(act, BbH, BbL, W0, b0, 96, tid, wid, lane);
    for (int l = 0; l < 3; l++)
        run_layer<16, true>(act, BbH, BbL, Wh + l * 65536, bh + l * 256, 256, tid, wid, lane);

    // heads from x1 (= act): sigma (+ mu/sig for coarse); 64 samples -> 2 warps
    float* rf = RF + ((size_t)ray * 128 + mbase) * 6;
    if (wid < 2) {
        int m = wid * 32 + lane;   // 0..63
        float s0 = 0.0f, s1 = 0.0f, s2 = 0.0f;
        for (int k = 0; k < 256; k++) {
            float xv = act[(size_t)k * ACT_STRIDE + m];
            s0 += xv * __ldg(Ws + k);
            if (COARSE) {
                s1 += xv * __ldg(Wm + 2 * k);
                s2 += xv * __ldg(Wm + 2 * k + 1);
            }
        }
        rf[m * 6 + 3] = s0 + __ldg(bs);
        if (COARSE) {
            rf[m * 6 + 4] = s1 + __ldg(bm);
            rf[m * 6 + 5] = s2 + __ldg(bm + 1);
        }
    }
    __syncthreads();

    run_layer<16, false>(act, BbH, BbL, Wb, bb, 256, tid, wid, lane);
    run_layer<8, true>(act, BbH, BbL, Wd, rbias_all + (size_t)ray * 128, 256, tid, wid, lane);

    // rgb head from h (= act rows 0..127)
    if (wid < 2) {
        int m = wid * 32 + lane;
        float r = 0.0f, gg = 0.0f, b = 0.0f;
        for (int k = 0; k < 128; k++) {
            float hv = act[(size_t)k * ACT_STRIDE + m];
            r  += hv * __ldg(Wr + 3 * k);
            gg += hv * __ldg(Wr + 3 * k + 1);
            b  += hv * __ldg(Wr + 3 * k + 2);
        }
        rf[m * 6 + 0] = r  + __ldg(br);
        rf[m * 6 + 1] = gg + __ldg(br + 1);
        rf[m * 6 + 2] = b  + __ldg(br + 2);
    }
}

// ---------------- coarse volume render + PDF ingredients ----------------
__global__ void vrender_coarse_kernel(float* __restrict__ out) {
    int r = blockIdx.x * blockDim.x + threadIdx.x;
    if (r >= NRAYS) return;
    float nrm = g_raynorm[r];
    float T = 1.0f, cr = 0.0f, cg = 0.0f, cb = 0.0f;
    for (int i = 0; i < 128; i++) {
        const float* f = g_rf + (size_t)(r * 128 + i) * 6;
        float t0 = 2.0f + 4.0f * ((float)i / 128.0f);
        float t1 = 2.0f + 4.0f * ((float)(i + 1) / 128.0f);
        float sr = fast_sigmoid(f[0]);
        float sg = fast_sigmoid(f[1]);
        float sb = fast_sigmoid(f[2]);
        float sigma = fmaxf(f[3], 0.0f);
        float alpha = 1.0f - __expf(-sigma * (t1 - t0) * nrm);
        float w = alpha * T;
        T *= (1.0f - alpha + 1e-10f);
        cr += w * sr; cg += w * sg; cb += w * sb;
        int si = r * 128 + i;
        g_weights[si] = w;
        float mu = fast_sigmoid(f[4]);
        float ss = (fast_sigmoid(f[5]) + 0.001f) * 2.0f;
        g_mus[si] = mu;
        g_smsig[si] = ss;
        float l = acdf_((0.0f - mu) / ss);
        g_lt[si] = l;
        g_pib[si] = acdf_((1.0f - mu) / ss) - l;
    }
    out[r * 3 + 0] = cr;
    out[r * 3 + 1] = cg;
    out[r * 3 + 2] = cb;
}

// ---------------- per-ray normalized CDF / PDF ----------------
__global__ void cdf_kernel() {
    int r = blockIdx.x * blockDim.x + threadIdx.x;
    if (r >= NRAYS) return;
    float sum = 0.0f;
    for (int i = 0; i < 128; i++) sum += g_weights[r * 128 + i] + 1e-5f;
    float inv = 1.0f / sum;
    g_cdf[r * 129] = 0.0f;
    float run = 0.0f;
    for (int i = 0; i < 128; i++) {
        float w = (g_weights[r * 128 + i] + 1e-5f) * inv;
        g_pdfn[r * 128 + i] = w;
        run += w;
        g_cdf[r * 129 + i + 1] = run;
    }
}

// ---------------- parallel inverse-CDF fine sampling ----------------
__global__ void fine_sample_kernel() {
    int t = blockIdx.x * blockDim.x + threadIdx.x;
    if (t >= NRAYS * 129) return;
    int r = t / 129;
    int i = t - r * 129;
    const float step = (1.0f - 1e-5f) / 128.0f;
    float u = step * (float)i;
    const float* cdf = g_cdf + r * 129;
    int lo = 0, hi = 128;
    while (lo < hi) {
        int mid = (lo + hi + 1) >> 1;
        if (cdf[mid] <= u) lo = mid; else hi = mid - 1;
    }
    int idx = lo < 127 ? lo : 127;
    float pdfv = g_pdfn[r * 128 + idx];
    float frac = (u - cdf[idx]) / fmaxf(pdfv, 1e-10f);
    frac = fminf(fmaxf(frac, 0.0f), 1.0f);
    int si = r * 128 + idx;
    float p = g_lt[si] + frac * g_pib[si];
    p = fminf(fmaxf(p, 1e-5f), 1.0f - 1e-5f);
    float x = g_mus[si] + g_smsig[si] * 1.4142135623730951f * erfinvf(2.0f * p - 1.0f);
    x = fminf(fmaxf(x, 0.0f), 1.0f);
    float b0 = 2.0f + 4.0f * ((float)idx / 128.0f);
    float b1 = 2.0f + 4.0f * ((float)(idx + 1) / 128.0f);
    g_tfine[r * 129 + i] = b0 + x * (b1 - b0);
}

// ---------------- fine volume render ----------------
__global__ void vrender_fine_kernel(float* __restrict__ out) {
    int r = blockIdx.x * blockDim.x + threadIdx.x;
    if (r >= NRAYS) return;
    float nrm = g_raynorm[r];
    float T = 1.0f, cr = 0.0f, cg = 0.0f, cb = 0.0f, dep = 0.0f, acc = 0.0f;
    for (int i = 0; i < 128; i++) {
        const float* f = g_rf + (size_t)(r * 128 + i) * 6;
        float t0 = g_tfine[r * 129 + i];
        float t1 = g_tfine[r * 129 + i + 1];
        float sr = fast_sigmoid(f[0]);
        float sg = fast_sigmoid(f[1]);
        float sb = fast_sigmoid(f[2]);
        float sigma = fmaxf(f[3], 0.0f);
        float alpha = 1.0f - __expf(-sigma * (t1 - t0) * nrm);
        float w = alpha * T;
        T *= (1.0f - alpha + 1e-10f);
        cr += w * sr; cg += w * sg; cb += w * sb;
        dep += w * 0.5f * (t0 + t1);
        acc += w;
    }
    out[6144 + r * 3 + 0] = cr;
    out[6144 + r * 3 + 1] = cg;
    out[6144 + r * 3 + 2] = cb;
    out[12288 + r] = dep;
    out[14336 + r] = acc;
}

// ---------------- host orchestration ----------------
extern "C" void kernel_launch(void* const* d_in, const int* in_sizes, int n_in,
                              void* d_out, int out_size)
{
    (void)out_size;
    const float* ro = (const float*)d_in[0];
    const float* rd = (const float*)d_in[1];
    const float* rr = (const float*)d_in[2];

    bool sigOrder = (n_in > 15 && in_sizes[15] == 512);
    int fb = sigOrder ? 17 : 15;
    int mb = sigOrder ? 15 : 27;

    const float* cW0 = (const float*)d_in[3];
    const float* cb0 = (const float*)d_in[4];
    const float* cWh = (const float*)d_in[5];
    const float* cbh = (const float*)d_in[6];
    const float* cWs = (const float*)d_in[7];
    const float* cbs = (const float*)d_in[8];
    const float* cWb = (const float*)d_in[9];
    const float* cbb = (const float*)d_in[10];
    const float* cWd = (const float*)d_in[11];
    const float* cbd = (const float*)d_in[12];
    const float* cWr = (const float*)d_in[13];
    const float* cbr = (const float*)d_in[14];
    const float* cWm = (const float*)d_in[mb];
    const float* cbm = (const float*)d_in[mb + 1];
    const float* fW0 = (const float*)d_in[fb + 0];
    const float* fb0 = (const float*)d_in[fb + 1];
    const float* fWh = (const float*)d_in[fb + 2];
    const float* fbh = (const float*)d_in[fb + 3];
    const float* fWs = (const float*)d_in[fb + 4];
    const float* fbs = (const float*)d_in[fb + 5];
    const float* fWb = (const float*)d_in[fb + 6];
    const float* fbb = (const float*)d_in[fb + 7];
    const float* fWd = (const float*)d_in[fb + 8];
    const float* fbd = (const float*)d_in[fb + 9];
    const float* fWr = (const float*)d_in[fb + 10];
    const float* fbr = (const float*)d_in[fb + 11];

    float *p_enc, *p_rf, *p_raybias, *p_tfine;
    cudaGetSymbolAddress((void**)&p_enc, g_enc);
    cudaGetSymbolAddress((void**)&p_rf, g_rf);
    cudaGetSymbolAddress((void**)&p_raybias, g_raybias);
    cudaGetSymbolAddress((void**)&p_tfine, g_tfine);

    cudaFuncSetAttribute(fused_mlp<true>,  cudaFuncAttributeMaxDynamicSharedMemorySize, FUSED_SMEM);
    cudaFuncSetAttribute(fused_mlp<false>, cudaFuncAttributeMaxDynamicSharedMemorySize, FUSED_SMEM);

    float* out = (float*)d_out;

    ray_setup_kernel<<<(NRAYS + 127) / 128, 128>>>(rd);

    // ================= coarse pass =================
    ipe_kernel<<<NS / 128, 128>>>(ro, rd, rr, nullptr);
    ray_bias_kernel<<<NRAYS, 128>>>(cWd, cbd);
    fused_mlp<true><<<NRAYS * 2, 256, FUSED_SMEM>>>(
        p_enc, cW0, cb0, cWh, cbh, cWs, cbs, cWm, cbm,
        cWb, cbb, cWd, p_raybias, cWr, cbr, p_rf);
    vrender_coarse_kernel<<<(NRAYS + 127) / 128, 128>>>(out);
    cdf_kernel<<<(NRAYS + 127) / 128, 128>>>();
    fine_sample_kernel<<<(NRAYS * 129 + 255) / 256, 256>>>();

    // ================= fine pass =================
    ipe_kernel<<<NS / 128, 128>>>(ro, rd, rr, p_tfine);
    ray_bias_kernel<<<NRAYS, 128>>>(fWd, fbd);
    fused_mlp<false><<<NRAYS * 2, 256, FUSED_SMEM>>>(
        p_enc, fW0, fb0, fWh, fbh, fWs, fbs, nullptr, nullptr,
        fWb, fbb, fWd, p_raybias, fWr, fbr, p_rf);
    vrender_fine_kernel<<<(NRAYS + 127) / 128, 128>>>(out);
}

// round 14
// speedup vs baseline: 1.0711x; 1.0711x over previous
#include <cuda_runtime.h>
#include <math.h>
#include <stdint.h>
#include <stddef.h>

#define NRAYS 2048
#define NSAMP 128
#define NS (NRAYS * NSAMP)   // 262144 samples per pass

// ---------------- static scratch (no allocations allowed) ----------------
__device__ float g_enc[NRAYS * 96 * 128];   // block-transposed IPE: [ray][k][m]
__device__ float g_rf[NS * 6];              // raw heads per sample
__device__ float g_direnc[NRAYS * 27];
__device__ float g_raynorm[NRAYS];
__device__ float g_raybias[NRAYS * 128];
__device__ float g_weights[NS];
__device__ float g_mus[NS];
__device__ float g_smsig[NS];
__device__ float g_lt[NS];
__device__ float g_pib[NS];
__device__ float g_tfine[NRAYS * 129];
__device__ float g_cdf[NRAYS * 129];
__device__ float g_pdfn[NS];

// fused-kernel smem layout (all u32 words):
//   actH : 128 k2-rows x 136 (packed bf16x2 hi, k-pairs; 128 m cols + pad)
//   actL : 128 k2-rows x 136 (packed bf16x2 lo residual)
//   BpkH : 2 buf x 8 k2 x 264 (bf16x2)
//   BpkL : same
#define ACT_STRIDE 136
#define ACT_WORDS (128 * ACT_STRIDE)
#define BPK_WORDS (2 * 8 * 264)
#define FUSED_SMEM ((2 * ACT_WORDS + 2 * BPK_WORDS) * 4)   // 156160 B

// ---------------- helpers ----------------
__device__ __forceinline__ float fast_sigmoid(float x) {
    return 1.0f / (1.0f + __expf(-x));
}
__device__ __forceinline__ float acdf_(float x) {
    float x3 = x * x * x;
    float z = 0.7978845608028654f * (x + 0.044715f * x3);
    return 1.0f / (1.0f + __expf(-2.0f * z));
}
// pack {lower = bf16(x0) [k even], upper = bf16(x1) [k odd]}
__device__ __forceinline__ uint32_t pack_bf16x2(float x0, float x1) {
    uint32_t d;
    asm("cvt.rn.bf16x2.f32 %0, %1, %2;" : "=r"(d) : "f"(x1), "f"(x0));
    return d;
}
// split pair (x0, x1) into bf16 hi-pack + bf16 lo-pack (residuals)
__device__ __forceinline__ void split_pair(float x0, float x1, uint32_t& hpk, uint32_t& lpk) {
    hpk = pack_bf16x2(x0, x1);
    float h0 = __uint_as_float(hpk << 16);
    float h1 = __uint_as_float(hpk & 0xffff0000u);
    lpk = pack_bf16x2(x0 - h0, x1 - h1);
}
__device__ __forceinline__ float bf_lo(uint32_t u) { return __uint_as_float(u << 16); }
__device__ __forceinline__ float bf_hi(uint32_t u) { return __uint_as_float(u & 0xffff0000u); }

#define MMA_BF16(d, a0, a1, a2, a3, b0, b1)                                  \
    asm volatile(                                                            \
        "mma.sync.aligned.m16n8k16.row.col.f32.bf16.bf16.f32 "               \
        "{%0,%1,%2,%3}, {%4,%5,%6,%7}, {%8,%9}, {%0,%1,%2,%3};"              \
        : "+f"(d[0]), "+f"(d[1]), "+f"(d[2]), "+f"(d[3])                     \
        : "r"(a0), "r"(a1), "r"(a2), "r"(a3), "r"(b0), "r"(b1))

// ---------------- ray setup ----------------
__global__ void ray_setup_kernel(const float* __restrict__ rd) {
    int r = blockIdx.x * blockDim.x + threadIdx.x;
    if (r >= NRAYS) return;
    float x = rd[r * 3 + 0], y = rd[r * 3 + 1], z = rd[r * 3 + 2];
    float n = sqrtf(x * x + y * y + z * z);
    g_raynorm[r] = n;
    float inv = 1.0f / n;
    float v[3] = {x * inv, y * inv, z * inv};
    float* de = g_direnc + r * 27;
    de[0] = v[0]; de[1] = v[1]; de[2] = v[2];
#pragma unroll
    for (int f = 0; f < 4; f++) {
        float fr = (float)(1 << f);
#pragma unroll
        for (int k = 0; k < 3; k++) {
            float xx = v[k] * fr;
            de[3 + f * 3 + k]  = sinf(xx);
            de[15 + f * 3 + k] = cosf(xx);
        }
    }
}

// per-ray bias for Wd layer: bd[o] + sum_j direnc[j] * Wd[256+j][o]
__global__ void ray_bias_kernel(const float* __restrict__ Wd, const float* __restrict__ bd) {
    int r = blockIdx.x;
    int o = threadIdx.x;
    __shared__ float de[27];
    if (o < 27) de[o] = g_direnc[r * 27 + o];
    __syncthreads();
    float a = bd[o];
#pragma unroll
    for (int j = 0; j < 27; j++) a += de[j] * Wd[(256 + j) * 128 + o];
    g_raybias[r * 128 + o] = a;
}

// ---------------- IPE, block-transposed output [ray][k][m] ----------------
__global__ void ipe_kernel(const float* __restrict__ ro, const float* __restrict__ rd,
                           const float* __restrict__ rr, const float* __restrict__ tsrc) {
    int s = blockIdx.x * blockDim.x + threadIdx.x;
    if (s >= NS) return;
    int ray = s >> 7, i = s & 127;
    float t0, t1;
    if (tsrc) {
        t0 = tsrc[ray * 129 + i];
        t1 = tsrc[ray * 129 + i + 1];
    } else {
        t0 = 2.0f + 4.0f * ((float)i / 128.0f);
        t1 = 2.0f + 4.0f * ((float)(i + 1) / 128.0f);
    }
    float c  = 0.5f * (t0 + t1);
    float dd = 0.5f * (t1 - t0);
    float d2s = dd * dd;
    float d4  = d2s * d2s;
    float c2  = c * c;
    float denom = 3.0f * c2 + d2s;
    float t_mean = c + 2.0f * c * d2s / denom;
    float t_var  = d2s * (1.0f / 3.0f) - (4.0f / 15.0f) * (d4 * (12.0f * c2 - d2s)) / (denom * denom);
    float rrv = rr[ray];
    float r_var = rrv * rrv * (c2 * 0.25f + (5.0f / 12.0f) * d2s - (4.0f / 15.0f) * d4 / denom);

    float rdv[3] = {rd[ray * 3 + 0], rd[ray * 3 + 1], rd[ray * 3 + 2]};
    float rov[3] = {ro[ray * 3 + 0], ro[ray * 3 + 1], ro[ray * 3 + 2]};
    float dn2 = rdv[0] * rdv[0] + rdv[1] * rdv[1] + rdv[2] * rdv[2];
    float invd2 = 1.0f / fmaxf(dn2, 1e-10f);
    float mean[3], cov[3];
#pragma unroll
    for (int k = 0; k < 3; k++) {
        mean[k] = rov[k] + rdv[k] * t_mean;
        float dok = rdv[k] * rdv[k];
        cov[k] = t_var * dok + r_var * (1.0f - dok * invd2);
    }

    float* e = g_enc + (size_t)ray * 96 * 128;
    int m = i;
    float scale = 1.0f;
#pragma unroll 4
    for (int deg = 0; deg < 16; deg++) {
        float sc2 = scale * scale;
#pragma unroll
        for (int k = 0; k < 3; k++) {
            int idx = deg * 3 + k;
            float sv, cv;
            float yv = cov[k] * sc2;
            if (yv > 60.0f) {
                sv = 0.0f; cv = 0.0f;
            } else {
                float att = __expf(-0.5f * yv);
                float y = mean[k] * scale;
                double kd = rint((double)y * 0.15915494309189535);
                float rp = (float)((double)y - kd * 6.283185307179586);
                sv = __sinf(rp) * att;
                cv = __cosf(rp) * att;
            }
            e[(size_t)idx * 128 + m]        = sv;
            e[(size_t)(48 + idx) * 128 + m] = cv;
        }
        scale *= 2.0f;
    }
}

// ---------------- fused-MLP layer, bf16x3 m16n8k16, packed activations ----------------
// 512 threads, 16 warps as 8(m) x 2(n); warp tile m16 x (NT*8). N total = NT*16.
// actH/actL[k2][m] hold pre-split bf16x2 k-pairs (stride 136, conflict-free).
// W streamed from global, split hi/lo bf16x2 k-pairs at stash time.
template<int NT, bool RELU>
__device__ __forceinline__ void run_layer(
    uint32_t* __restrict__ actH, uint32_t* __restrict__ actL,
    uint32_t* __restrict__ BbH, uint32_t* __restrict__ BbL,
    const float* __restrict__ Wl, const float* __restrict__ bias,
    int K, int tid, int wid, int lane)
{
    constexpr int NCOLS = NT * 16;
    constexpr int PER = (8 * NCOLS) / 512;   // packed words per thread per stage (4 or 2)
    const int wm = (wid & 7) * 16;
    const int wn = (wid >> 3) * (NT * 8);
    const int g  = lane >> 2;
    const int t4 = lane & 3;

    const int idx0 = tid * PER;
    const int k2   = idx0 / NCOLS;           // 0..7
    const int nn   = idx0 % NCOLS;
    const float* Wr0 = Wl + (size_t)(2 * k2) * NCOLS + nn;
    const float* Wr1 = Wr0 + NCOLS;
    uint32_t* stH = BbH + k2 * 264 + nn;
    uint32_t* stL = BbL + k2 * 264 + nn;

    float d[NT][4];
#pragma unroll
    for (int nt = 0; nt < NT; nt++)
#pragma unroll
        for (int q = 0; q < 4; q++) d[nt][q] = 0.0f;

    const int nStage = K >> 4;

    float p0[PER], p1[PER];

    auto loadW = [&](int s) {
        const float* a0 = Wr0 + (size_t)s * 16 * NCOLS;
        const float* a1 = Wr1 + (size_t)s * 16 * NCOLS;
        if constexpr (PER == 4) {
            float4 u = *(const float4*)a0; p0[0]=u.x; p0[1]=u.y; p0[2]=u.z; p0[3]=u.w;
            float4 v = *(const float4*)a1; p1[0]=v.x; p1[1]=v.y; p1[2]=v.z; p1[3]=v.w;
        } else {
            float2 u = *(const float2*)a0; p0[0]=u.x; p0[1]=u.y;
            float2 v = *(const float2*)a1; p1[0]=v.x; p1[1]=v.y;
        }
    };
    auto stash = [&](int b) {
        uint32_t h[PER], l[PER];
#pragma unroll
        for (int j = 0; j < PER; j++) split_pair(p0[j], p1[j], h[j], l[j]);
        if constexpr (PER == 4) {
            *(uint4*)(stH + b * 2112) = make_uint4(h[0], h[1], h[2], h[3]);
            *(uint4*)(stL + b * 2112) = make_uint4(l[0], l[1], l[2], l[3]);
        } else {
            *(uint2*)(stH + b * 2112) = make_uint2(h[0], h[1]);
            *(uint2*)(stL + b * 2112) = make_uint2(l[0], l[1]);
        }
    };

    loadW(0);
    stash(0);
    __syncthreads();

    for (int s = 0; s < nStage; ++s) {
        const int buf = s & 1;
        if (s + 1 < nStage) loadW(s + 1);

        // A fragments: direct packed loads, zero ALU
        uint32_t aH[4], aL[4];
        {
            const uint32_t* H0 = actH + (size_t)(s * 8 + t4) * ACT_STRIDE;
            const uint32_t* H4 = H0 + 4 * ACT_STRIDE;
            const uint32_t* L0 = actL + (size_t)(s * 8 + t4) * ACT_STRIDE;
            const uint32_t* L4 = L0 + 4 * ACT_STRIDE;
            const int ma = wm + g, mb = ma + 8;
            aH[0] = H0[ma]; aH[1] = H0[mb]; aH[2] = H4[ma]; aH[3] = H4[mb];
            aL[0] = L0[ma]; aL[1] = L0[mb]; aL[2] = L4[ma]; aL[3] = L4[mb];
        }

        const uint32_t* bh = BbH + buf * 2112 + t4 * 264;
        const uint32_t* bl = BbL + buf * 2112 + t4 * 264;
#pragma unroll
        for (int nt = 0; nt < NT; nt++) {
            const int n0 = wn + nt * 8 + g;
            uint32_t bH0 = bh[n0];
            uint32_t bH1 = bh[4 * 264 + n0];
            uint32_t bL0 = bl[n0];
            uint32_t bL1 = bl[4 * 264 + n0];
            MMA_BF16(d[nt], aH[0], aH[1], aH[2], aH[3], bH0, bH1);
            MMA_BF16(d[nt], aL[0], aL[1], aL[2], aL[3], bH0, bH1);
            MMA_BF16(d[nt], aH[0], aH[1], aH[2], aH[3], bL0, bL1);
        }

        if (s + 1 < nStage) {
            stash(buf ^ 1);
            __syncthreads();
        }
    }

    __syncthreads();   // all act reads complete before overwrite

    // epilogue: split adjacent output pair (next layer's k-pair), store packed
#pragma unroll
    for (int nt = 0; nt < NT; nt++) {
        const int c0 = wn + nt * 8 + 2 * t4;
        const int c2 = c0 >> 1;              // k2 row for next layer
        const int r0 = wm + g;
        float b0v = bias[c0], b1v = bias[c0 + 1];
        float v0 = d[nt][0] + b0v;
        float v1 = d[nt][1] + b1v;
        float v2 = d[nt][2] + b0v;
        float v3 = d[nt][3] + b1v;
        if (RELU) {
            v0 = fmaxf(v0, 0.0f); v1 = fmaxf(v1, 0.0f);
            v2 = fmaxf(v2, 0.0f); v3 = fmaxf(v3, 0.0f);
        }
        uint32_t hp, lp, hp2, lp2;
        split_pair(v0, v1, hp, lp);
        split_pair(v2, v3, hp2, lp2);
        actH[(size_t)c2 * ACT_STRIDE + r0]     = hp;
        actL[(size_t)c2 * ACT_STRIDE + r0]     = lp;
        actH[(size_t)c2 * ACT_STRIDE + r0 + 8] = hp2;
        actL[(size_t)c2 * ACT_STRIDE + r0 + 8] = lp2;
    }
    __syncthreads();
}

// ---------------- fused MLP: one block = one ray (128 samples) ----------------
template<bool COARSE>
__global__ void __launch_bounds__(512, 1) fused_mlp(
    const float* __restrict__ enc_t,
    const float* __restrict__ W0, const float* __restrict__ b0,
    const float* __restrict__ Wh, const float* __restrict__ bh,
    const float* __restrict__ Ws, const float* __restrict__ bs,
    const float* __restrict__ Wm, const float* __restrict__ bm,
    const float* __restrict__ Wb, const float* __restrict__ bb,
    const float* __restrict__ Wd, const float* __restrict__ rbias_all,
    const float* __restrict__ Wr, const float* __restrict__ br,
    float* __restrict__ RF)
{
    extern __shared__ uint32_t smemu[];
    uint32_t* actH = smemu;
    uint32_t* actL = actH + ACT_WORDS;
    uint32_t* BbH  = actL + ACT_WORDS;
    uint32_t* BbL  = BbH + BPK_WORDS;

    const int tid  = threadIdx.x;
    const int wid  = tid >> 5;
    const int lane = tid & 31;
    const int blk  = blockIdx.x;

    // load enc tile [96][128] fp32 -> packed k-pairs into actH/actL
    {
        const float* ebase = enc_t + (size_t)blk * 96 * 128;
        for (int j = tid; j < 48 * 32; j += 512) {
            int k2 = j >> 5, m4 = (j & 31) * 4;
            const float* r0p = ebase + (size_t)(2 * k2) * 128 + m4;
            const float* r1p = r0p + 128;
            float4 a = *(const float4*)r0p;
            float4 b = *(const float4*)r1p;
            uint32_t h[4], l[4];
            split_pair(a.x, b.x, h[0], l[0]);
            split_pair(a.y, b.y, h[1], l[1]);
            split_pair(a.z, b.z, h[2], l[2]);
            split_pair(a.w, b.w, h[3], l[3]);
            *(uint4*)(actH + (size_t)k2 * ACT_STRIDE + m4) = make_uint4(h[0], h[1], h[2], h[3]);
            *(uint4*)(actL + (size_t)k2 * ACT_STRIDE + m4) = make_uint4(l[0], l[1], l[2], l[3]);
        }
    }
    __syncthreads();

    run_layer<16, true>(actH, actL, BbH, BbL, W0, b0, 96, tid, wid, lane);
    for (int l = 0; l < 3; l++)
        run_layer<16, true>(actH, actL, BbH, BbL, Wh + l * 65536, bh + l * 256, 256, tid, wid, lane);

    // heads from x1 (= act): sigma (+ mu/sig for coarse); x = hi + lo
    float* rf = RF + (size_t)blk * 128 * 6;
    if (wid < 4) {
        int m = wid * 32 + lane;
        float s0 = 0.0f, s1 = 0.0f, s2 = 0.0f;
        for (int k2 = 0; k2 < 128; k2++) {
            uint32_t hw = actH[(size_t)k2 * ACT_STRIDE + m];
            uint32_t lw = actL[(size_t)k2 * ACT_STRIDE + m];
            float x0 = bf_lo(hw) + bf_lo(lw);
            float x1 = bf_hi(hw) + bf_hi(lw);
            s0 += x0 * __ldg(Ws + 2 * k2) + x1 * __ldg(Ws + 2 * k2 + 1);
            if (COARSE) {
                s1 += x0 * __ldg(Wm + 4 * k2)     + x1 * __ldg(Wm + 4 * k2 + 2);
                s2 += x0 * __ldg(Wm + 4 * k2 + 1) + x1 * __ldg(Wm + 4 * k2 + 3);
            }
        }
        rf[m * 6 + 3] = s0 + __ldg(bs);
        if (COARSE) {
            rf[m * 6 + 4] = s1 + __ldg(bm);
            rf[m * 6 + 5] = s2 + __ldg(bm + 1);
        }
    }
    __syncthreads();

    run_layer<16, false>(actH, actL, BbH, BbL, Wb, bb, 256, tid, wid, lane);
    run_layer<8, true>(actH, actL, BbH, BbL, Wd, rbias_all + (size_t)blk * 128, 256, tid, wid, lane);

    // rgb head from h (= act k2 rows 0..63)
    if (wid < 4) {
        int m = wid * 32 + lane;
        float r = 0.0f, gg = 0.0f, b = 0.0f;
        for (int k2 = 0; k2 < 64; k2++) {
            uint32_t hw = actH[(size_t)k2 * ACT_STRIDE + m];
            uint32_t lw = actL[(size_t)k2 * ACT_STRIDE + m];
            float x0 = bf_lo(hw) + bf_lo(lw);
            float x1 = bf_hi(hw) + bf_hi(lw);
            r  += x0 * __ldg(Wr + 6 * k2)     + x1 * __ldg(Wr + 6 * k2 + 3);
            gg += x0 * __ldg(Wr + 6 * k2 + 1) + x1 * __ldg(Wr + 6 * k2 + 4);
            b  += x0 * __ldg(Wr + 6 * k2 + 2) + x1 * __ldg(Wr + 6 * k2 + 5);
        }
        rf[m * 6 + 0] = r  + __ldg(br);
        rf[m * 6 + 1] = gg + __ldg(br + 1);
        rf[m * 6 + 2] = b  + __ldg(br + 2);
    }
}

// ---------------- coarse volume render + PDF ingredients ----------------
__global__ void vrender_coarse_kernel(float* __restrict__ out) {
    int r = blockIdx.x * blockDim.x + threadIdx.x;
    if (r >= NRAYS) return;
    float nrm = g_raynorm[r];
    float T = 1.0f, cr = 0.0f, cg = 0.0f, cb = 0.0f;
    for (int i = 0; i < 128; i++) {
        const float* f = g_rf + (size_t)(r * 128 + i) * 6;
        float t0 = 2.0f + 4.0f * ((float)i / 128.0f);
        float t1 = 2.0f + 4.0f * ((float)(i + 1) / 128.0f);
        float sr = fast_sigmoid(f[0]);
        float sg = fast_sigmoid(f[1]);
        float sb = fast_sigmoid(f[2]);
        float sigma = fmaxf(f[3], 0.0f);
        float alpha = 1.0f - __expf(-sigma * (t1 - t0) * nrm);
        float w = alpha * T;
        T *= (1.0f - alpha + 1e-10f);
        cr += w * sr; cg += w * sg; cb += w * sb;
        int si = r * 128 + i;
        g_weights[si] = w;
        float mu = fast_sigmoid(f[4]);
        float ss = (fast_sigmoid(f[5]) + 0.001f) * 2.0f;
        g_mus[si] = mu;
        g_smsig[si] = ss;
        float l = acdf_((0.0f - mu) / ss);
        g_lt[si] = l;
        g_pib[si] = acdf_((1.0f - mu) / ss) - l;
    }
    out[r * 3 + 0] = cr;
    out[r * 3 + 1] = cg;
    out[r * 3 + 2] = cb;
}

// ---------------- per-ray normalized CDF / PDF ----------------
__global__ void cdf_kernel() {
    int r = blockIdx.x * blockDim.x + threadIdx.x;
    if (r >= NRAYS) return;
    float sum = 0.0f;
    for (int i = 0; i < 128; i++) sum += g_weights[r * 128 + i] + 1e-5f;
    float inv = 1.0f / sum;
    g_cdf[r * 129] = 0.0f;
    float run = 0.0f;
    for (int i = 0; i < 128; i++) {
        float w = (g_weights[r * 128 + i] + 1e-5f) * inv;
        g_pdfn[r * 128 + i] = w;
        run += w;
        g_cdf[r * 129 + i + 1] = run;
    }
}

// ---------------- parallel inverse-CDF fine sampling ----------------
__global__ void fine_sample_kernel() {
    int t = blockIdx.x * blockDim.x + threadIdx.x;
    if (t >= NRAYS * 129) return;
    int r = t / 129;
    int i = t - r * 129;
    const float step = (1.0f - 1e-5f) / 128.0f;
    float u = step * (float)i;
    const float* cdf = g_cdf + r * 129;
    int lo = 0, hi = 128;
    while (lo < hi) {
        int mid = (lo + hi + 1) >> 1;
        if (cdf[mid] <= u) lo = mid; else hi = mid - 1;
    }
    int idx = lo < 127 ? lo : 127;
    float pdfv = g_pdfn[r * 128 + idx];
    float frac = (u - cdf[idx]) / fmaxf(pdfv, 1e-10f);
    frac = fminf(fmaxf(frac, 0.0f), 1.0f);
    int si = r * 128 + idx;
    float p = g_lt[si] + frac * g_pib[si];
    p = fminf(fmaxf(p, 1e-5f), 1.0f - 1e-5f);
    float x = g_mus[si] + g_smsig[si] * 1.4142135623730951f * erfinvf(2.0f * p - 1.0f);
    x = fminf(fmaxf(x, 0.0f), 1.0f);
    float b0 = 2.0f + 4.0f * ((float)idx / 128.0f);
    float b1 = 2.0f + 4.0f * ((float)(idx + 1) / 128.0f);
    g_tfine[r * 129 + i] = b0 + x * (b1 - b0);
}

// ---------------- fine volume render ----------------
__global__ void vrender_fine_kernel(float* __restrict__ out) {
    int r = blockIdx.x * blockDim.x + threadIdx.x;
    if (r >= NRAYS) return;
    float nrm = g_raynorm[r];
    float T = 1.0f, cr = 0.0f, cg = 0.0f, cb = 0.0f, dep = 0.0f, acc = 0.0f;
    for (int i = 0; i < 128; i++) {
        const float* f = g_rf + (size_t)(r * 128 + i) * 6;
        float t0 = g_tfine[r * 129 + i];
        float t1 = g_tfine[r * 129 + i + 1];
        float sr = fast_sigmoid(f[0]);
        float sg = fast_sigmoid(f[1]);
        float sb = fast_sigmoid(f[2]);
        float sigma = fmaxf(f[3], 0.0f);
        float alpha = 1.0f - __expf(-sigma * (t1 - t0) * nrm);
        float w = alpha * T;
        T *= (1.0f - alpha + 1e-10f);
        cr += w * sr; cg += w * sg; cb += w * sb;
        dep += w * 0.5f * (t0 + t1);
        acc += w;
    }
    out[6144 + r * 3 + 0] = cr;
    out[6144 + r * 3 + 1] = cg;
    out[6144 + r * 3 + 2] = cb;
    out[12288 + r] = dep;
    out[14336 + r] = acc;
}

// ---------------- host orchestration ----------------
extern "C" void kernel_launch(void* const* d_in, const int* in_sizes, int n_in,
                              void* d_out, int out_size)
{
    (void)out_size;
    const float* ro = (const float*)d_in[0];
    const float* rd = (const float*)d_in[1];
    const float* rr = (const float*)d_in[2];

    bool sigOrder = (n_in > 15 && in_sizes[15] == 512);
    int fb = sigOrder ? 17 : 15;
    int mb = sigOrder ? 15 : 27;

    const float* cW0 = (const float*)d_in[3];
    const float* cb0 = (const float*)d_in[4];
    const float* cWh = (const float*)d_in[5];
    const float* cbh = (const float*)d_in[6];
    const float* cWs = (const float*)d_in[7];
    const float* cbs = (const float*)d_in[8];
    const float* cWb = (const float*)d_in[9];
    const float* cbb = (const float*)d_in[10];
    const float* cWd = (const float*)d_in[11];
    const float* cbd = (const float*)d_in[12];
    const float* cWr = (const float*)d_in[13];
    const float* cbr = (const float*)d_in[14];
    const float* cWm = (const float*)d_in[mb];
    const float* cbm = (const float*)d_in[mb + 1];
    const float* fW0 = (const float*)d_in[fb + 0];
    const float* fb0 = (const float*)d_in[fb + 1];
    const float* fWh = (const float*)d_in[fb + 2];
    const float* fbh = (const float*)d_in[fb + 3];
    const float* fWs = (const float*)d_in[fb + 4];
    const float* fbs = (const float*)d_in[fb + 5];
    const float* fWb = (const float*)d_in[fb + 6];
    const float* fbb = (const float*)d_in[fb + 7];
    const float* fWd = (const float*)d_in[fb + 8];
    const float* fbd = (const float*)d_in[fb + 9];
    const float* fWr = (const float*)d_in[fb + 10];
    const float* fbr = (const float*)d_in[fb + 11];

    float *p_enc, *p_rf, *p_raybias, *p_tfine;
    cudaGetSymbolAddress((void**)&p_enc, g_enc);
    cudaGetSymbolAddress((void**)&p_rf, g_rf);
    cudaGetSymbolAddress((void**)&p_raybias, g_raybias);
    cudaGetSymbolAddress((void**)&p_tfine, g_tfine);

    cudaFuncSetAttribute(fused_mlp<true>,  cudaFuncAttributeMaxDynamicSharedMemorySize, FUSED_SMEM);
    cudaFuncSetAttribute(fused_mlp<false>, cudaFuncAttributeMaxDynamicSharedMemorySize, FUSED_SMEM);

    float* out = (float*)d_out;

    ray_setup_kernel<<<(NRAYS + 127) / 128, 128>>>(rd);

    // ================= coarse pass =================
    ipe_kernel<<<NS / 128, 128>>>(ro, rd, rr, nullptr);
    ray_bias_kernel<<<NRAYS, 128>>>(cWd, cbd);
    fused_mlp<true><<<NRAYS, 512, FUSED_SMEM>>>(
        p_enc, cW0, cb0, cWh, cbh, cWs, cbs, cWm, cbm,
        cWb, cbb, cWd, p_raybias, cWr, cbr, p_rf);
    vrender_coarse_kernel<<<(NRAYS + 127) / 128, 128>>>(out);
    cdf_kernel<<<(NRAYS + 127) / 128, 128>>>();
    fine_sample_kernel<<<(NRAYS * 129 + 255) / 256, 256>>>();

    // ================= fine pass =================
    ipe_kernel<<<NS / 128, 128>>>(ro, rd, rr, p_tfine);
    ray_bias_kernel<<<NRAYS, 128>>>(fWd, fbd);
    fused_mlp<false><<<NRAYS, 512, FUSED_SMEM>>>(
        p_enc, fW0, fb0, fWh, fbh, fWs, fbs, nullptr, nullptr,
        fWb, fbb, fWd, p_raybias, fWr, fbr, p_rf);
    vrender_fine_kernel<<<(NRAYS + 127) / 128, 128>>>(out);
}

// round 15
// speedup vs baseline: 1.6306x; 1.5224x over previous
#include <cuda_runtime.h>
#include <math.h>
#include <stdint.h>
#include <stddef.h>

#define NRAYS 2048
#define NSAMP 128
#define NS (NRAYS * NSAMP)   // 262144 samples per pass

// ---------------- static scratch (no allocations allowed) ----------------
__device__ float g_enc[NRAYS * 96 * 128];   // block-transposed IPE: [ray][k][m]
__device__ float g_rf[NS * 6];              // raw heads per sample
__device__ float g_direnc[NRAYS * 27];
__device__ float g_raynorm[NRAYS];
__device__ float g_raybias[NRAYS * 128];
__device__ float g_weights[NS];
__device__ float g_mus[NS];
__device__ float g_smsig[NS];
__device__ float g_lt[NS];
__device__ float g_pib[NS];
__device__ float g_tfine[NRAYS * 129];
__device__ float g_cdf[NRAYS * 129];
__device__ float g_pdfn[NS];

// fused-kernel smem layout:
//   act  : 256 x 132 fp32                    (135168 B)
//   BpkH : 2 buf x 8 k2 x 264 u32 (bf16x2)   ( 16896 B)
//   BpkL : same                              ( 16896 B)
#define ACT_STRIDE 132
#define ACT_WORDS (256 * ACT_STRIDE)
#define BPK_WORDS (2 * 8 * 264)
#define FUSED_SMEM ((ACT_WORDS + 2 * BPK_WORDS) * 4)   // 168960 B

// ---------------- helpers ----------------
__device__ __forceinline__ float fast_sigmoid(float x) {
    return 1.0f / (1.0f + __expf(-x));
}
__device__ __forceinline__ float acdf_(float x) {
    float x3 = x * x * x;
    float z = 0.7978845608028654f * (x + 0.044715f * x3);
    return 1.0f / (1.0f + __expf(-2.0f * z));
}
// pack {lower = bf16(x0) [k even], upper = bf16(x1) [k odd]}
__device__ __forceinline__ uint32_t pack_bf16x2(float x0, float x1) {
    uint32_t d;
    asm("cvt.rn.bf16x2.f32 %0, %1, %2;" : "=r"(d) : "f"(x1), "f"(x0));
    return d;
}
// split pair (x0, x1) into bf16 hi-pack + bf16 lo-pack (residuals)
__device__ __forceinline__ void split_pair(float x0, float x1, uint32_t& hpk, uint32_t& lpk) {
    hpk = pack_bf16x2(x0, x1);
    float h0 = __uint_as_float(hpk << 16);
    float h1 = __uint_as_float(hpk & 0xffff0000u);
    lpk = pack_bf16x2(x0 - h0, x1 - h1);
}
__device__ __forceinline__ void cp16(void* s, const void* g) {
    uint32_t sa = (uint32_t)__cvta_generic_to_shared(s);
    asm volatile("cp.async.ca.shared.global [%0], [%1], 16;" :: "r"(sa), "l"(g));
}
__device__ __forceinline__ void cp_commit() {
    asm volatile("cp.async.commit_group;" ::: "memory");
}
__device__ __forceinline__ void cp_wait0() {
    asm volatile("cp.async.wait_group 0;" ::: "memory");
}

#define MMA_BF16(d, a0, a1, a2, a3, b0, b1)                                  \
    asm volatile(                                                            \
        "mma.sync.aligned.m16n8k16.row.col.f32.bf16.bf16.f32 "               \
        "{%0,%1,%2,%3}, {%4,%5,%6,%7}, {%8,%9}, {%0,%1,%2,%3};"              \
        : "+f"(d[0]), "+f"(d[1]), "+f"(d[2]), "+f"(d[3])                     \
        : "r"(a0), "r"(a1), "r"(a2), "r"(a3), "r"(b0), "r"(b1))

// ---------------- ray setup ----------------
__global__ void ray_setup_kernel(const float* __restrict__ rd) {
    int r = blockIdx.x * blockDim.x + threadIdx.x;
    if (r >= NRAYS) return;
    float x = rd[r * 3 + 0], y = rd[r * 3 + 1], z = rd[r * 3 + 2];
    float n = sqrtf(x * x + y * y + z * z);
    g_raynorm[r] = n;
    float inv = 1.0f / n;
    float v[3] = {x * inv, y * inv, z * inv};
    float* de = g_direnc + r * 27;
    de[0] = v[0]; de[1] = v[1]; de[2] = v[2];
#pragma unroll
    for (int f = 0; f < 4; f++) {
        float fr = (float)(1 << f);
#pragma unroll
        for (int k = 0; k < 3; k++) {
            float xx = v[k] * fr;
            de[3 + f * 3 + k]  = sinf(xx);
            de[15 + f * 3 + k] = cosf(xx);
        }
    }
}

// per-ray bias for Wd layer: bd[o] + sum_j direnc[j] * Wd[256+j][o]
__global__ void ray_bias_kernel(const float* __restrict__ Wd, const float* __restrict__ bd) {
    int r = blockIdx.x;
    int o = threadIdx.x;
    __shared__ float de[27];
    if (o < 27) de[o] = g_direnc[r * 27 + o];
    __syncthreads();
    float a = bd[o];
#pragma unroll
    for (int j = 0; j < 27; j++) a += de[j] * Wd[(256 + j) * 128 + o];
    g_raybias[r * 128 + o] = a;
}

// ---------------- IPE, block-transposed output [ray][k][m] ----------------
__global__ void ipe_kernel(const float* __restrict__ ro, const float* __restrict__ rd,
                           const float* __restrict__ rr, const float* __restrict__ tsrc) {
    int s = blockIdx.x * blockDim.x + threadIdx.x;
    if (s >= NS) return;
    int ray = s >> 7, i = s & 127;
    float t0, t1;
    if (tsrc) {
        t0 = tsrc[ray * 129 + i];
        t1 = tsrc[ray * 129 + i + 1];
    } else {
        t0 = 2.0f + 4.0f * ((float)i / 128.0f);
        t1 = 2.0f + 4.0f * ((float)(i + 1) / 128.0f);
    }
    float c  = 0.5f * (t0 + t1);
    float dd = 0.5f * (t1 - t0);
    float d2s = dd * dd;
    float d4  = d2s * d2s;
    float c2  = c * c;
    float denom = 3.0f * c2 + d2s;
    float t_mean = c + 2.0f * c * d2s / denom;
    float t_var  = d2s * (1.0f / 3.0f) - (4.0f / 15.0f) * (d4 * (12.0f * c2 - d2s)) / (denom * denom);
    float rrv = rr[ray];
    float r_var = rrv * rrv * (c2 * 0.25f + (5.0f / 12.0f) * d2s - (4.0f / 15.0f) * d4 / denom);

    float rdv[3] = {rd[ray * 3 + 0], rd[ray * 3 + 1], rd[ray * 3 + 2]};
    float rov[3] = {ro[ray * 3 + 0], ro[ray * 3 + 1], ro[ray * 3 + 2]};
    float dn2 = rdv[0] * rdv[0] + rdv[1] * rdv[1] + rdv[2] * rdv[2];
    float invd2 = 1.0f / fmaxf(dn2, 1e-10f);
    float mean[3], cov[3];
#pragma unroll
    for (int k = 0; k < 3; k++) {
        mean[k] = rov[k] + rdv[k] * t_mean;
        float dok = rdv[k] * rdv[k];
        cov[k] = t_var * dok + r_var * (1.0f - dok * invd2);
    }

    float* e = g_enc + (size_t)ray * 96 * 128;
    int m = i;
    float scale = 1.0f;
#pragma unroll 4
    for (int deg = 0; deg < 16; deg++) {
        float sc2 = scale * scale;
#pragma unroll
        for (int k = 0; k < 3; k++) {
            int idx = deg * 3 + k;
            float sv, cv;
            float yv = cov[k] * sc2;
            if (yv > 60.0f) {
                sv = 0.0f; cv = 0.0f;
            } else {
                float att = __expf(-0.5f * yv);
                float y = mean[k] * scale;
                double kd = rint((double)y * 0.15915494309189535);
                float rp = (float)((double)y - kd * 6.283185307179586);
                sv = __sinf(rp) * att;
                cv = __cosf(rp) * att;
            }
            e[(size_t)idx * 128 + m]        = sv;
            e[(size_t)(48 + idx) * 128 + m] = cv;
        }
        scale *= 2.0f;
    }
}

// ---------------- fused-MLP layer, bf16x3 m16n8k16 ----------------
// 512 threads, 16 warps as 4(m) x 4(n); warp tile m32 x (NCOLS/4).
// 2 m-tiles per warp halves B-fragment re-reads vs 8m x 2n.
// act[k][m] raw fp32, stride 132; A split to bf16 hi/lo at fragment load.
// W streamed, split hi/lo bf16x2-packed by k-pairs at stash time.
template<int NCOLS, bool RELU>
__device__ __forceinline__ void run_layer(
    float* __restrict__ act, uint32_t* __restrict__ BbH, uint32_t* __restrict__ BbL,
    const float* __restrict__ Wl, const float* __restrict__ bias,
    int K, int tid, int wid, int lane)
{
    constexpr int NTW = NCOLS / 32;          // n8-tiles per warp (8 or 4)
    constexpr int PER = (8 * NCOLS) / 512;   // packed words per thread per stage (4 or 2)
    const int wm = (wid & 3) * 32;           // warp m offset (2 x m16 tiles)
    const int wn = (wid >> 2) * (NCOLS / 4); // warp n offset
    const int g  = lane >> 2;
    const int t4 = lane & 3;

    const int idx0 = tid * PER;
    const int k2   = idx0 / NCOLS;           // 0..7
    const int nn   = idx0 % NCOLS;
    const float* Wr0 = Wl + (size_t)(2 * k2) * NCOLS + nn;
    const float* Wr1 = Wr0 + NCOLS;
    uint32_t* stH = BbH + k2 * 264 + nn;
    uint32_t* stL = BbL + k2 * 264 + nn;

    float d[2][NTW][4];
#pragma unroll
    for (int mt = 0; mt < 2; mt++)
#pragma unroll
        for (int nt = 0; nt < NTW; nt++)
#pragma unroll
            for (int q = 0; q < 4; q++) d[mt][nt][q] = 0.0f;

    const int nStage = K >> 4;

    float p0[PER], p1[PER];

    auto loadW = [&](int s) {
        const float* a0 = Wr0 + (size_t)s * 16 * NCOLS;
        const float* a1 = Wr1 + (size_t)s * 16 * NCOLS;
        if constexpr (PER == 4) {
            float4 u = *(const float4*)a0; p0[0]=u.x; p0[1]=u.y; p0[2]=u.z; p0[3]=u.w;
            float4 v = *(const float4*)a1; p1[0]=v.x; p1[1]=v.y; p1[2]=v.z; p1[3]=v.w;
        } else {
            float2 u = *(const float2*)a0; p0[0]=u.x; p0[1]=u.y;
            float2 v = *(const float2*)a1; p1[0]=v.x; p1[1]=v.y;
        }
    };
    auto stash = [&](int b) {
        uint32_t h[PER], l[PER];
#pragma unroll
        for (int j = 0; j < PER; j++) split_pair(p0[j], p1[j], h[j], l[j]);
        if constexpr (PER == 4) {
            *(uint4*)(stH + b * 2112) = make_uint4(h[0], h[1], h[2], h[3]);
            *(uint4*)(stL + b * 2112) = make_uint4(l[0], l[1], l[2], l[3]);
        } else {
            *(uint2*)(stH + b * 2112) = make_uint2(h[0], h[1]);
            *(uint2*)(stL + b * 2112) = make_uint2(l[0], l[1]);
        }
    };

    loadW(0);
    stash(0);
    __syncthreads();

    for (int s = 0; s < nStage; ++s) {
        const int buf = s & 1;
        if (s + 1 < nStage) loadW(s + 1);

        // A fragments: k-pairs split to bf16 hi/lo at load, both m-tiles
        uint32_t aH[2][4], aL[2][4];
        {
            const float* A0 = act + (size_t)(s * 16 + 2 * t4) * ACT_STRIDE;
            const float* A8 = A0 + 8 * ACT_STRIDE;
#pragma unroll
            for (int mt = 0; mt < 2; mt++) {
                const int ma = wm + mt * 16 + g, mb = ma + 8;
                split_pair(A0[ma], A0[ACT_STRIDE + ma], aH[mt][0], aL[mt][0]);
                split_pair(A0[mb], A0[ACT_STRIDE + mb], aH[mt][1], aL[mt][1]);
                split_pair(A8[ma], A8[ACT_STRIDE + ma], aH[mt][2], aL[mt][2]);
                split_pair(A8[mb], A8[ACT_STRIDE + mb], aH[mt][3], aL[mt][3]);
            }
        }

        const uint32_t* bh = BbH + buf * 2112 + t4 * 264;
        const uint32_t* bl = BbL + buf * 2112 + t4 * 264;
#pragma unroll
        for (int nt = 0; nt < NTW; nt++) {
            const int n0 = wn + nt * 8 + g;
            uint32_t bH0 = bh[n0];
            uint32_t bH1 = bh[4 * 264 + n0];
            uint32_t bL0 = bl[n0];
            uint32_t bL1 = bl[4 * 264 + n0];
#pragma unroll
            for (int mt = 0; mt < 2; mt++) {
                MMA_BF16(d[mt][nt], aH[mt][0], aH[mt][1], aH[mt][2], aH[mt][3], bH0, bH1);
                MMA_BF16(d[mt][nt], aL[mt][0], aL[mt][1], aL[mt][2], aL[mt][3], bH0, bH1);
                MMA_BF16(d[mt][nt], aH[mt][0], aH[mt][1], aH[mt][2], aH[mt][3], bL0, bL1);
            }
        }

        if (s + 1 < nStage) {
            stash(buf ^ 1);
            __syncthreads();
        }
    }

    __syncthreads();   // all act reads complete before overwrite

    // transposed epilogue: act[col][row] = activation(value + bias)
#pragma unroll
    for (int mt = 0; mt < 2; mt++) {
#pragma unroll
        for (int nt = 0; nt < NTW; nt++) {
            const int c0 = wn + nt * 8 + 2 * t4;
            const int r0 = wm + mt * 16 + g;
            float b0v = bias[c0], b1v = bias[c0 + 1];
            float v0 = d[mt][nt][0] + b0v;
            float v1 = d[mt][nt][1] + b1v;
            float v2 = d[mt][nt][2] + b0v;
            float v3 = d[mt][nt][3] + b1v;
            if (RELU) {
                v0 = fmaxf(v0, 0.0f); v1 = fmaxf(v1, 0.0f);
                v2 = fmaxf(v2, 0.0f); v3 = fmaxf(v3, 0.0f);
            }
            act[(size_t)c0 * ACT_STRIDE + r0]           = v0;
            act[(size_t)(c0 + 1) * ACT_STRIDE + r0]     = v1;
            act[(size_t)c0 * ACT_STRIDE + r0 + 8]       = v2;
            act[(size_t)(c0 + 1) * ACT_STRIDE + r0 + 8] = v3;
        }
    }
    __syncthreads();
}

// ---------------- fused MLP: one block = one ray (128 samples) ----------------
template<bool COARSE>
__global__ void __launch_bounds__(512, 1) fused_mlp(
    const float* __restrict__ enc_t,
    const float* __restrict__ W0, const float* __restrict__ b0,
    const float* __restrict__ Wh, const float* __restrict__ bh,
    const float* __restrict__ Ws, const float* __restrict__ bs,
    const float* __restrict__ Wm, const float* __restrict__ bm,
    const float* __restrict__ Wb, const float* __restrict__ bb,
    const float* __restrict__ Wd, const float* __restrict__ rbias_all,
    const float* __restrict__ Wr, const float* __restrict__ br,
    float* __restrict__ RF)
{
    extern __shared__ float smem[];
    float* act = smem;
    uint32_t* BbH = (uint32_t*)(smem + ACT_WORDS);
    uint32_t* BbL = BbH + BPK_WORDS;

    const int tid  = threadIdx.x;
    const int wid  = tid >> 5;
    const int lane = tid & 31;
    const int blk  = blockIdx.x;

    // load enc tile [96][128] into act
    {
        const float* ebase = enc_t + (size_t)blk * 96 * 128;
        for (int i = tid; i < 96 * 32; i += 512) {
            int k = i >> 5, m4 = (i & 31) * 4;
            cp16(act + (size_t)k * ACT_STRIDE + m4, ebase + k * 128 + m4);
        }
        cp_commit(); cp_wait0();
    }
    __syncthreads();

    run_layer<256, true>(act, BbH, BbL, W0, b0, 96, tid, wid, lane);
    for (int l = 0; l < 3; l++)
        run_layer<256, true>(act, BbH, BbL, Wh + l * 65536, bh + l * 256, 256, tid, wid, lane);

    // heads from x1 (= act): sigma (+ mu/sig for coarse)
    float* rf = RF + (size_t)blk * 128 * 6;
    if (wid < 4) {
        int m = wid * 32 + lane;
        float s0 = 0.0f, s1 = 0.0f, s2 = 0.0f;
        for (int k = 0; k < 256; k++) {
            float xv = act[(size_t)k * ACT_STRIDE + m];
            s0 += xv * __ldg(Ws + k);
            if (COARSE) {
                s1 += xv * __ldg(Wm + 2 * k);
                s2 += xv * __ldg(Wm + 2 * k + 1);
            }
        }
        rf[m * 6 + 3] = s0 + __ldg(bs);
        if (COARSE) {
            rf[m * 6 + 4] = s1 + __ldg(bm);
            rf[m * 6 + 5] = s2 + __ldg(bm + 1);
        }
    }
    __syncthreads();

    run_layer<256, false>(act, BbH, BbL, Wb, bb, 256, tid, wid, lane);
    run_layer<128, true>(act, BbH, BbL, Wd, rbias_all + (size_t)blk * 128, 256, tid, wid, lane);

    // rgb head from h (= act rows 0..127)
    if (wid < 4) {
        int m = wid * 32 + lane;
        float r = 0.0f, gg = 0.0f, b = 0.0f;
        for (int k = 0; k < 128; k++) {
            float hv = act[(size_t)k * ACT_STRIDE + m];
            r  += hv * __ldg(Wr + 3 * k);
            gg += hv * __ldg(Wr + 3 * k + 1);
            b  += hv * __ldg(Wr + 3 * k + 2);
        }
        rf[m * 6 + 0] = r  + __ldg(br);
        rf[m * 6 + 1] = gg + __ldg(br + 1);
        rf[m * 6 + 2] = b  + __ldg(br + 2);
    }
}

// ---------------- coarse volume render + PDF ingredients ----------------
__global__ void vrender_coarse_kernel(float* __restrict__ out) {
    int r = blockIdx.x * blockDim.x + threadIdx.x;
    if (r >= NRAYS) return;
    float nrm = g_raynorm[r];
    float T = 1.0f, cr = 0.0f, cg = 0.0f, cb = 0.0f;
    for (int i = 0; i < 128; i++) {
        const float* f = g_rf + (size_t)(r * 128 + i) * 6;
        float t0 = 2.0f + 4.0f * ((float)i / 128.0f);
        float t1 = 2.0f + 4.0f * ((float)(i + 1) / 128.0f);
        float sr = fast_sigmoid(f[0]);
        float sg = fast_sigmoid(f[1]);
        float sb = fast_sigmoid(f[2]);
        float sigma = fmaxf(f[3], 0.0f);
        float alpha = 1.0f - __expf(-sigma * (t1 - t0) * nrm);
        float w = alpha * T;
        T *= (1.0f - alpha + 1e-10f);
        cr += w * sr; cg += w * sg; cb += w * sb;
        int si = r * 128 + i;
        g_weights[si] = w;
        float mu = fast_sigmoid(f[4]);
        float ss = (fast_sigmoid(f[5]) + 0.001f) * 2.0f;
        g_mus[si] = mu;
        g_smsig[si] = ss;
        float l = acdf_((0.0f - mu) / ss);
        g_lt[si] = l;
        g_pib[si] = acdf_((1.0f - mu) / ss) - l;
    }
    out[r * 3 + 0] = cr;
    out[r * 3 + 1] = cg;
    out[r * 3 + 2] = cb;
}

// ---------------- per-ray normalized CDF / PDF ----------------
__global__ void cdf_kernel() {
    int r = blockIdx.x * blockDim.x + threadIdx.x;
    if (r >= NRAYS) return;
    float sum = 0.0f;
    for (int i = 0; i < 128; i++) sum += g_weights[r * 128 + i] + 1e-5f;
    float inv = 1.0f / sum;
    g_cdf[r * 129] = 0.0f;
    float run = 0.0f;
    for (int i = 0; i < 128; i++) {
        float w = (g_weights[r * 128 + i] + 1e-5f) * inv;
        g_pdfn[r * 128 + i] = w;
        run += w;
        g_cdf[r * 129 + i + 1] = run;
    }
}

// ---------------- parallel inverse-CDF fine sampling ----------------
__global__ void fine_sample_kernel() {
    int t = blockIdx.x * blockDim.x + threadIdx.x;
    if (t >= NRAYS * 129) return;
    int r = t / 129;
    int i = t - r * 129;
    const float step = (1.0f - 1e-5f) / 128.0f;
    float u = step * (float)i;
    const float* cdf = g_cdf + r * 129;
    int lo = 0, hi = 128;
    while (lo < hi) {
        int mid = (lo + hi + 1) >> 1;
        if (cdf[mid] <= u) lo = mid; else hi = mid - 1;
    }
    int idx = lo < 127 ? lo : 127;
    float pdfv = g_pdfn[r * 128 + idx];
    float frac = (u - cdf[idx]) / fmaxf(pdfv, 1e-10f);
    frac = fminf(fmaxf(frac, 0.0f), 1.0f);
    int si = r * 128 + idx;
    float p = g_lt[si] + frac * g_pib[si];
    p = fminf(fmaxf(p, 1e-5f), 1.0f - 1e-5f);
    float x = g_mus[si] + g_smsig[si] * 1.4142135623730951f * erfinvf(2.0f * p - 1.0f);
    x = fminf(fmaxf(x, 0.0f), 1.0f);
    float b0 = 2.0f + 4.0f * ((float)idx / 128.0f);
    float b1 = 2.0f + 4.0f * ((float)(idx + 1) / 128.0f);
    g_tfine[r * 129 + i] = b0 + x * (b1 - b0);
}

// ---------------- fine volume render ----------------
__global__ void vrender_fine_kernel(float* __restrict__ out) {
    int r = blockIdx.x * blockDim.x + threadIdx.x;
    if (r >= NRAYS) return;
    float nrm = g_raynorm[r];
    float T = 1.0f, cr = 0.0f, cg = 0.0f, cb = 0.0f, dep = 0.0f, acc = 0.0f;
    for (int i = 0; i < 128; i++) {
        const float* f = g_rf + (size_t)(r * 128 + i) * 6;
        float t0 = g_tfine[r * 129 + i];
        float t1 = g_tfine[r * 129 + i + 1];
        float sr = fast_sigmoid(f[0]);
        float sg = fast_sigmoid(f[1]);
        float sb = fast_sigmoid(f[2]);
        float sigma = fmaxf(f[3], 0.0f);
        float alpha = 1.0f - __expf(-sigma * (t1 - t0) * nrm);
        float w = alpha * T;
        T *= (1.0f - alpha + 1e-10f);
        cr += w * sr; cg += w * sg; cb += w * sb;
        dep += w * 0.5f * (t0 + t1);
        acc += w;
    }
    out[6144 + r * 3 + 0] = cr;
    out[6144 + r * 3 + 1] = cg;
    out[6144 + r * 3 + 2] = cb;
    out[12288 + r] = dep;
    out[14336 + r] = acc;
}

// ---------------- host orchestration ----------------
extern "C" void kernel_launch(void* const* d_in, const int* in_sizes, int n_in,
                              void* d_out, int out_size)
{
    (void)out_size;
    const float* ro = (const float*)d_in[0];
    const float* rd = (const float*)d_in[1];
    const float* rr = (const float*)d_in[2];

    bool sigOrder = (n_in > 15 && in_sizes[15] == 512);
    int fb = sigOrder ? 17 : 15;
    int mb = sigOrder ? 15 : 27;

    const float* cW0 = (const float*)d_in[3];
    const float* cb0 = (const float*)d_in[4];
    const float* cWh = (const float*)d_in[5];
    const float* cbh = (const float*)d_in[6];
    const float* cWs = (const float*)d_in[7];
    const float* cbs = (const float*)d_in[8];
    const float* cWb = (const float*)d_in[9];
    const float* cbb = (const float*)d_in[10];
    const float* cWd = (const float*)d_in[11];
    const float* cbd = (const float*)d_in[12];
    const float* cWr = (const float*)d_in[13];
    const float* cbr = (const float*)d_in[14];
    const float* cWm = (const float*)d_in[mb];
    const float* cbm = (const float*)d_in[mb + 1];
    const float* fW0 = (const float*)d_in[fb + 0];
    const float* fb0 = (const float*)d_in[fb + 1];
    const float* fWh = (const float*)d_in[fb + 2];
    const float* fbh = (const float*)d_in[fb + 3];
    const float* fWs = (const float*)d_in[fb + 4];
    const float* fbs = (const float*)d_in[fb + 5];
    const float* fWb = (const float*)d_in[fb + 6];
    const float* fbb = (const float*)d_in[fb + 7];
    const float* fWd = (const float*)d_in[fb + 8];
    const float* fbd = (const float*)d_in[fb + 9];
    const float* fWr = (const float*)d_in[fb + 10];
    const float* fbr = (const float*)d_in[fb + 11];

    float *p_enc, *p_rf, *p_raybias, *p_tfine;
    cudaGetSymbolAddress((void**)&p_enc, g_enc);
    cudaGetSymbolAddress((void**)&p_rf, g_rf);
    cudaGetSymbolAddress((void**)&p_raybias, g_raybias);
    cudaGetSymbolAddress((void**)&p_tfine, g_tfine);

    cudaFuncSetAttribute(fused_mlp<true>,  cudaFuncAttributeMaxDynamicSharedMemorySize, FUSED_SMEM);
    cudaFuncSetAttribute(fused_mlp<false>, cudaFuncAttributeMaxDynamicSharedMemorySize, FUSED_SMEM);

    float* out = (float*)d_out;

    ray_setup_kernel<<<(NRAYS + 127) / 128, 128>>>(rd);

    // ================= coarse pass =================
    ipe_kernel<<<NS / 128, 128>>>(ro, rd, rr, nullptr);
    ray_bias_kernel<<<NRAYS, 128>>>(cWd, cbd);
    fused_mlp<true><<<NRAYS, 512, FUSED_SMEM>>>(
        p_enc, cW0, cb0, cWh, cbh, cWs, cbs, cWm, cbm,
        cWb, cbb, cWd, p_raybias, cWr, cbr, p_rf);
    vrender_coarse_kernel<<<(NRAYS + 127) / 128, 128>>>(out);
    cdf_kernel<<<(NRAYS + 127) / 128, 128>>>();
    fine_sample_kernel<<<(NRAYS * 129 + 255) / 256, 256>>>();

    // ================= fine pass =================
    ipe_kernel<<<NS / 128, 128>>>(ro, rd, rr, p_tfine);
    ray_bias_kernel<<<NRAYS, 128>>>(fWd, fbd);
    fused_mlp<false><<<NRAYS, 512, FUSED_SMEM>>>(
        p_enc, fW0, fb0, fWh, fbh, fWs, fbs, nullptr, nullptr,
        fWb, fbb, fWd, p_raybias, fWr, fbr, p_rf);
    vrender_fine_kernel<<<(NRAYS + 127) / 128, 128>>>(out);
}